// round 2
// baseline (speedup 1.0000x reference)
#include <cuda_runtime.h>
#include <cuda_bf16.h>

// Problem constants (fixed by the reference).
#define NROWS   2000000
#define DIM     128
#define NCLS    1000
#define DECAY   0.3f

// Tiling: 6784-row chunks -> 295 CTAs (~2 waves over 148 SMs).
#define CHUNK   6784
#define NBLK    ((NROWS + CHUNK - 1) / CHUNK)   // 295
#define THREADS 512                              // 16 warps/CTA

// Scratch accumulators (allocation-free: __device__ globals).
__device__ __align__(16) float g_sums[NCLS * DIM];
__device__ float    g_counts[NCLS];
__device__ unsigned g_present[NCLS];

__global__ void init_kernel() {
    int i = blockIdx.x * blockDim.x + threadIdx.x;
    if (i < NCLS * DIM) g_sums[i] = 0.0f;
    if (i < NCLS) { g_counts[i] = 0.0f; g_present[i] = 0u; }
}

__global__ __launch_bounds__(THREADS) void accum_kernel(
    const float* __restrict__ x,
    const int* __restrict__ y,
    const int* __restrict__ mask)   // bool exported as int32
{
    __shared__ unsigned       s_hist[1024];   // padded to 1024 for the scan
    __shared__ unsigned       s_off[1024];
    __shared__ unsigned       s_cur[NCLS];
    __shared__ unsigned       s_warp[16];
    __shared__ unsigned short s_bin[CHUNK];   // chunk-local row offsets

    const int tid    = threadIdx.x;
    const int row0   = blockIdx.x * CHUNK;
    const int rowEnd = min(row0 + CHUNK, NROWS);
    const unsigned lane = tid & 31;
    const unsigned wid  = tid >> 5;

    // ---- Phase 1: class histogram of this chunk ----
    s_hist[tid]       = 0u;
    s_hist[tid + 512] = 0u;
    __syncthreads();
    for (int i = row0 + tid; i < rowEnd; i += THREADS)
        atomicAdd(&s_hist[y[i]], 1u);
    __syncthreads();

    // ---- Phase 2: exclusive scan over 1024 entries (2 per thread) ----
    unsigned h0 = s_hist[2 * tid];
    unsigned h1 = s_hist[2 * tid + 1];
    unsigned v  = h0 + h1;
    unsigned inc = v;
    #pragma unroll
    for (int o = 1; o < 32; o <<= 1) {
        unsigned n = __shfl_up_sync(0xFFFFFFFFu, inc, o);
        if (lane >= (unsigned)o) inc += n;
    }
    if (lane == 31) s_warp[wid] = inc;
    __syncthreads();
    if (wid == 0) {
        unsigned wv = (lane < 16) ? s_warp[lane] : 0u;
        #pragma unroll
        for (int o = 1; o < 16; o <<= 1) {
            unsigned n = __shfl_up_sync(0xFFFFFFFFu, wv, o);
            if (lane >= (unsigned)o) wv += n;
        }
        if (lane < 16) s_warp[lane] = wv;
    }
    __syncthreads();
    unsigned excl = inc - v + (wid ? s_warp[wid - 1] : 0u);
    s_off[2 * tid]     = excl;
    s_off[2 * tid + 1] = excl + h0;
    if (2 * tid     < NCLS) s_cur[2 * tid]     = excl;
    if (2 * tid + 1 < NCLS) s_cur[2 * tid + 1] = excl + h0;
    __syncthreads();

    // ---- Phase 3: scatter row offsets into class bins ----
    for (int i = row0 + tid; i < rowEnd; i += THREADS) {
        unsigned p = atomicAdd(&s_cur[y[i]], 1u);
        s_bin[p] = (unsigned short)(i - row0);
    }
    __syncthreads();

    // ---- Phase 4: one warp per class (strided): gather + register accumulate,
    //      then a single red.global.add.v4.f32 per (CTA, class). ----
    const float4* __restrict__ x4 = (const float4*)x;
    for (int c = (int)wid; c < NCLS; c += 16) {
        unsigned k = s_hist[c];
        if (!k) continue;
        unsigned base = s_off[c];

        float4 a0 = make_float4(0.f, 0.f, 0.f, 0.f);
        float4 a1 = make_float4(0.f, 0.f, 0.f, 0.f);
        float cnt = 0.f;

        unsigned j = 0;
        for (; j + 2 <= k; j += 2) {
            int i0 = row0 + (int)s_bin[base + j];
            int i1 = row0 + (int)s_bin[base + j + 1];
            float m0 = mask[i0] ? 1.f : 0.f;
            float m1 = mask[i1] ? 1.f : 0.f;
            float4 v0 = x4[(size_t)i0 * 32 + lane];
            float4 v1 = x4[(size_t)i1 * 32 + lane];
            a0.x += v0.x * m0; a0.y += v0.y * m0; a0.z += v0.z * m0; a0.w += v0.w * m0;
            a1.x += v1.x * m1; a1.y += v1.y * m1; a1.z += v1.z * m1; a1.w += v1.w * m1;
            cnt += m0 + m1;
        }
        if (j < k) {
            int i0 = row0 + (int)s_bin[base + j];
            float m0 = mask[i0] ? 1.f : 0.f;
            float4 v0 = x4[(size_t)i0 * 32 + lane];
            a0.x += v0.x * m0; a0.y += v0.y * m0; a0.z += v0.z * m0; a0.w += v0.w * m0;
            cnt += m0;
        }
        a0.x += a1.x; a0.y += a1.y; a0.z += a1.z; a0.w += a1.w;

        float* dst = &g_sums[c * DIM + lane * 4];
        asm volatile("red.global.add.v4.f32 [%0], {%1, %2, %3, %4};"
                     :: "l"(dst), "f"(a0.x), "f"(a0.y), "f"(a0.z), "f"(a0.w)
                     : "memory");
        if (lane == 0) {
            atomicAdd(&g_counts[c], cnt);
            g_present[c] = 1u;   // racing identical stores: fine
        }
    }
}

__global__ void finalize_kernel(const float* __restrict__ centroids,
                                float* __restrict__ out)
{
    int idx = blockIdx.x * blockDim.x + threadIdx.x;
    if (idx >= NCLS * DIM) return;
    int c = idx >> 7;
    float cent = centroids[idx];
    float r = cent;
    if (g_present[c]) {
        float cntv = fmaxf(g_counts[c], 1.0f);
        r = DECAY * (g_sums[idx] / cntv) + (1.0f - DECAY) * cent;
    }
    out[idx] = r;
}

extern "C" void kernel_launch(void* const* d_in, const int* in_sizes, int n_in,
                              void* d_out, int out_size)
{
    const float* x         = (const float*)d_in[0];
    const int*   y         = (const int*)d_in[1];
    const int*   mask      = (const int*)d_in[2];
    const float* centroids = (const float*)d_in[3];
    float*       out       = (float*)d_out;

    init_kernel<<<(NCLS * DIM + 255) / 256, 256>>>();
    accum_kernel<<<NBLK, THREADS>>>(x, y, mask);
    finalize_kernel<<<(NCLS * DIM + 255) / 256, 256>>>(centroids, out);
}

// round 3
// speedup vs baseline: 1.2945x; 1.2945x over previous
#include <cuda_runtime.h>
#include <cuda_bf16.h>

// Problem constants (fixed by the reference).
#define NROWS   2000000
#define DIM     128
#define NCLS    1000
#define DECAY   0.3f

// One wave: 148 CTAs x 1024 threads, 13514-row chunks (148*13514 = 2000072).
#define NBLK    148
#define CHUNK   13514
#define THREADS 1024

// Scratch accumulators (allocation-free: __device__ globals).
__device__ __align__(16) float g_sums[NCLS * DIM];
__device__ float    g_counts[NCLS];
__device__ unsigned g_present[NCLS];

__global__ void init_kernel() {
    int i = blockIdx.x * blockDim.x + threadIdx.x;
    if (i < NCLS * DIM) g_sums[i] = 0.0f;
    if (i < NCLS) { g_counts[i] = 0.0f; g_present[i] = 0u; }
}

__global__ __launch_bounds__(THREADS, 1) void accum_kernel(
    const float* __restrict__ x,
    const int* __restrict__ y,
    const int* __restrict__ mask)   // bool exported as int32
{
    __shared__ unsigned       s_hist[1024];   // padded to 1024 for the scan
    __shared__ unsigned       s_off[1024];
    __shared__ unsigned       s_cur[NCLS];
    __shared__ unsigned       s_warp[32];
    __shared__ unsigned short s_bin[CHUNK];   // chunk-local row offsets (masked rows only)

    const int tid    = threadIdx.x;
    const int row0   = blockIdx.x * CHUNK;
    const int rowEnd = min(row0 + CHUNK, NROWS);
    const unsigned lane = tid & 31;
    const unsigned wid  = tid >> 5;

    // ---- Phase 1: full (unmasked) class histogram of this chunk ----
    s_hist[tid] = 0u;
    __syncthreads();
    for (int i = row0 + tid; i < rowEnd; i += THREADS)
        atomicAdd(&s_hist[y[i]], 1u);
    __syncthreads();

    // ---- Phase 2: exclusive scan over 1024 entries (1 per thread) ----
    unsigned v   = s_hist[tid];
    unsigned inc = v;
    #pragma unroll
    for (int o = 1; o < 32; o <<= 1) {
        unsigned n = __shfl_up_sync(0xFFFFFFFFu, inc, o);
        if (lane >= (unsigned)o) inc += n;
    }
    if (lane == 31) s_warp[wid] = inc;
    __syncthreads();
    if (wid == 0) {
        unsigned wv = s_warp[lane];
        #pragma unroll
        for (int o = 1; o < 32; o <<= 1) {
            unsigned n = __shfl_up_sync(0xFFFFFFFFu, wv, o);
            if (lane >= (unsigned)o) wv += n;
        }
        s_warp[lane] = wv;
    }
    __syncthreads();
    unsigned excl = inc - v + (wid ? s_warp[wid - 1] : 0u);
    s_off[tid] = excl;
    if (tid < NCLS) s_cur[tid] = excl;
    __syncthreads();

    // ---- Phase 3: scatter MASKED row offsets into class bins ----
    for (int i = row0 + tid; i < rowEnd; i += THREADS) {
        int c = y[i];
        if (mask[i]) {
            unsigned p = atomicAdd(&s_cur[c], 1u);
            s_bin[p] = (unsigned short)(i - row0);
        }
    }
    __syncthreads();

    // ---- Phase 4: one warp per class (strided): unroll-4 gather, no mask,
    //      then one red.global.add.v4.f32 per (CTA, class). ----
    const float4* __restrict__ x4 = (const float4*)x;
    for (int c = (int)wid; c < NCLS; c += 32) {
        unsigned h    = s_hist[c];          // unmasked presence
        unsigned base = s_off[c];
        unsigned k    = s_cur[c] - base;    // masked count

        if (lane == 0) {
            if (h) g_present[c] = 1u;       // racing identical stores: fine
            if (k) atomicAdd(&g_counts[c], (float)k);
        }
        if (!k) continue;

        float4 a0 = make_float4(0.f, 0.f, 0.f, 0.f);
        float4 a1 = make_float4(0.f, 0.f, 0.f, 0.f);
        float4 a2 = make_float4(0.f, 0.f, 0.f, 0.f);
        float4 a3 = make_float4(0.f, 0.f, 0.f, 0.f);

        unsigned j = 0;
        for (; j + 4 <= k; j += 4) {
            int i0 = row0 + (int)s_bin[base + j];
            int i1 = row0 + (int)s_bin[base + j + 1];
            int i2 = row0 + (int)s_bin[base + j + 2];
            int i3 = row0 + (int)s_bin[base + j + 3];
            float4 v0 = __ldcs(&x4[(size_t)i0 * 32 + lane]);
            float4 v1 = __ldcs(&x4[(size_t)i1 * 32 + lane]);
            float4 v2 = __ldcs(&x4[(size_t)i2 * 32 + lane]);
            float4 v3 = __ldcs(&x4[(size_t)i3 * 32 + lane]);
            a0.x += v0.x; a0.y += v0.y; a0.z += v0.z; a0.w += v0.w;
            a1.x += v1.x; a1.y += v1.y; a1.z += v1.z; a1.w += v1.w;
            a2.x += v2.x; a2.y += v2.y; a2.z += v2.z; a2.w += v2.w;
            a3.x += v3.x; a3.y += v3.y; a3.z += v3.z; a3.w += v3.w;
        }
        for (; j < k; j++) {
            int i0 = row0 + (int)s_bin[base + j];
            float4 v0 = __ldcs(&x4[(size_t)i0 * 32 + lane]);
            a0.x += v0.x; a0.y += v0.y; a0.z += v0.z; a0.w += v0.w;
        }
        a0.x += a1.x + a2.x + a3.x;
        a0.y += a1.y + a2.y + a3.y;
        a0.z += a1.z + a2.z + a3.z;
        a0.w += a1.w + a2.w + a3.w;

        float* dst = &g_sums[c * DIM + lane * 4];
        asm volatile("red.global.add.v4.f32 [%0], {%1, %2, %3, %4};"
                     :: "l"(dst), "f"(a0.x), "f"(a0.y), "f"(a0.z), "f"(a0.w)
                     : "memory");
    }
}

__global__ void finalize_kernel(const float* __restrict__ centroids,
                                float* __restrict__ out)
{
    int idx = blockIdx.x * blockDim.x + threadIdx.x;
    if (idx >= NCLS * DIM) return;
    int c = idx >> 7;
    float cent = centroids[idx];
    float r = cent;
    if (g_present[c]) {
        float cntv = fmaxf(g_counts[c], 1.0f);
        r = DECAY * (g_sums[idx] / cntv) + (1.0f - DECAY) * cent;
    }
    out[idx] = r;
}

extern "C" void kernel_launch(void* const* d_in, const int* in_sizes, int n_in,
                              void* d_out, int out_size)
{
    const float* x         = (const float*)d_in[0];
    const int*   y         = (const int*)d_in[1];
    const int*   mask      = (const int*)d_in[2];
    const float* centroids = (const float*)d_in[3];
    float*       out       = (float*)d_out;

    init_kernel<<<(NCLS * DIM + 255) / 256, 256>>>();
    accum_kernel<<<NBLK, THREADS>>>(x, y, mask);
    finalize_kernel<<<(NCLS * DIM + 255) / 256, 256>>>(centroids, out);
}